// round 5
// baseline (speedup 1.0000x reference)
#include <cuda_runtime.h>
#include <cstdint>

// NCC loss, 9x9 box, SAME zero pad, n=81 (matches reference conv).
// Round 5: pipeline-granularity attack.
//   - 9-row stages (== ring period): slot index static in the same 9-step unroll.
//   - double-buffered 9-row stages, cp.async prefetch distance ~2 stages (~2300cyc).
//   - one (possibly empty) commit per iteration -> constant wait_group 1 is exact.
//   - barriers 48 -> 16.
// Math identical to Round 4 (rel_err ~6e-8). Deterministic fused reduction.

#define WW 512
#define HH 512
#define NB 32
#define COLS 128
#define STRIPH 64
#define NBLK (4 * 8 * 32)   // 1024 blocks
#define NSTG 8              // 72 row-steps / 9 rows per stage
#define VECS_PER_STAGE 918  // 27 row-images * 34 float4

__device__ float        g_partials[NBLK];
__device__ unsigned int g_count = 0;

__device__ __forceinline__ void cp16(uint32_t dst, const float* src, bool ok) {
    asm volatile("cp.async.cg.shared.global [%0], [%1], 16, %2;"
                 :: "r"(dst), "l"(src), "r"(ok ? 16 : 0) : "memory");
}
__device__ __forceinline__ void cp_commit() {
    asm volatile("cp.async.commit_group;" ::: "memory");
}
__device__ __forceinline__ void cp_wait1() {
    asm volatile("cp.async.wait_group 1;" ::: "memory");
}

__global__ __launch_bounds__(128, 5)
void ncc_fused(const float* __restrict__ img1,
               const float* __restrict__ img2,
               const float* __restrict__ fus,
               float* __restrict__ out)
{
    const int tid   = threadIdx.x;
    const int xbase = blockIdx.x * COLS;
    const int ybase = blockIdx.y * STRIPH;
    const int b     = blockIdx.z;

    const size_t base = (size_t)b * (size_t)(HH * WW);
    const float* p1 = img1 + base;
    const float* p2 = img2 + base;
    const float* pf = fus  + base;

    // 2 buffers x 27 row-images (img-major: [img][jj]) x 136 floats
    __shared__ float rows[2][27][136];
    __shared__ float red[4];
    __shared__ int   lastflag;

    const uint32_t smem_rows = (uint32_t)__cvta_generic_to_shared(&rows[0][0][0]);

    // ---- stage s into buffer buf: 918 float4 cp.asyncs (no commit here) ----
    auto stage = [&](int s, int buf) {
        const int r0 = ybase - 4 + 9 * s;
#pragma unroll
        for (int it = 0; it < 8; ++it) {
            const int i = tid + 128 * it;
            if (i < VECS_PER_STAGE) {
                const int ri  = i / 34;            // row-image 0..26 = img*9 + jj
                const int vec = i - ri * 34;
                const int img = ri / 9;
                const int jj  = ri - img * 9;
                const int r   = r0 + jj;
                const int gx  = xbase - 4 + vec * 4;
                const bool ok = (r >= 0) && (r < HH) && (gx >= 0) && (gx < WW);
                const int rc  = r < 0 ? 0 : (r >= HH ? HH - 1 : r);
                const int gxc = gx < 0 ? 0 : (gx > WW - 4 ? WW - 4 : gx);
                const float* p = (img == 0) ? p1 : ((img == 1) ? p2 : pf);
                const uint32_t dst =
                    smem_rows + (uint32_t)(((buf * 27 + ri) * 136 + vec * 4) * 4);
                cp16(dst, p + (long)rc * WW + gxc, ok);
            }
        }
    };

    float ring[9][8];
    float S[8];
#pragma unroll
    for (int j = 0; j < 9; ++j)
#pragma unroll
        for (int q = 0; q < 8; ++q) ring[j][q] = 0.0f;
#pragma unroll
    for (int q = 0; q < 8; ++q) S[q] = 0.0f;

    float acc = 0.0f;
    const float inv_n = 1.0f / 81.0f;

    stage(0, 0); cp_commit();
    stage(1, 1); cp_commit();

    for (int s = 0; s < NSTG; ++s) {
        // groups issued so far = 2 + s; stage s is group #s; later groups = 1
        // (stage s+1, or an empty group). So wait_group 1 <=> stage s landed.
        cp_wait1();
        __syncthreads();           // staged data visible to all threads

        const float (*R)[136] = rows[s & 1];

#pragma unroll
        for (int j = 0; j < 9; ++j) {       // slot == j (static): (9s+j)%9 == j
            // ---- horizontal 9-tap sums of the 8 fields ----
            float h0 = 0.f, h1 = 0.f, h2 = 0.f, h3 = 0.f;
            float h4 = 0.f, h5 = 0.f, h6 = 0.f, h7 = 0.f;
#pragma unroll
            for (int k = 0; k < 9; ++k) {
                const float av = R[j][tid + k];
                const float cv = R[9 + j][tid + k];
                const float fv = R[18 + j][tid + k];
                h0 += av;
                h1 = fmaf(av, av, h1);
                h2 = fmaf(av, fv, h2);
                h3 += cv;
                h4 = fmaf(cv, cv, h4);
                h5 = fmaf(cv, fv, h5);
                h6 += fv;
                h7 = fmaf(fv, fv, h7);
            }

            // ---- vertical slide (static ring slot j) ----
            S[0] += h0 - ring[j][0]; ring[j][0] = h0;
            S[1] += h1 - ring[j][1]; ring[j][1] = h1;
            S[2] += h2 - ring[j][2]; ring[j][2] = h2;
            S[3] += h3 - ring[j][3]; ring[j][3] = h3;
            S[4] += h4 - ring[j][4]; ring[j][4] = h4;
            S[5] += h5 - ring[j][5]; ring[j][5] = h5;
            S[6] += h6 - ring[j][6]; ring[j][6] = h6;
            S[7] += h7 - ring[j][7]; ring[j][7] = h7;

            // ---- emit output row (row-step i = 9s+j >= 8) ----
            if (s != 0 || j == 8) {
                const float mA = S[0] * inv_n;
                const float mB = S[3] * inv_n;
                const float mJ = S[6] * inv_n;
                const float crossA = fmaf(-mA, S[6], S[2]);
                const float varA   = fmaf(-mA, S[0], S[1]);
                const float varJ   = fmaf(-mJ, S[6], S[7]);
                const float crossB = fmaf(-mB, S[6], S[5]);
                const float varB   = fmaf(-mB, S[3], S[4]);
                const float ccA = crossA * crossA *
                                  __fdividef(1.0f, fmaf(varA, varJ, 1e-5f));
                const float ccB = crossB * crossB *
                                  __fdividef(1.0f, fmaf(varB, varJ, 1e-5f));
                acc += (2.0f - ccA - ccB);   // 2 * combined
            }
        }

        __syncthreads();                       // all warps done reading buf s&1
        if (s + 2 < NSTG) stage(s + 2, s & 1); // refill the buffer just consumed
        cp_commit();                           // always: keeps group count uniform
    }

    // ---- deterministic block reduction ----
#pragma unroll
    for (int off = 16; off > 0; off >>= 1)
        acc += __shfl_xor_sync(0xffffffffu, acc, off);
    if ((tid & 31) == 0) red[tid >> 5] = acc;
    __syncthreads();

    const int bidx = (blockIdx.z * 8 + blockIdx.y) * 4 + blockIdx.x;
    if (tid == 0) {
        g_partials[bidx] = (red[0] + red[1]) + (red[2] + red[3]);
        __threadfence();
        unsigned int old = atomicInc(&g_count, NBLK - 1);  // wraps: graph-replay safe
        lastflag = (old == NBLK - 1);
    }
    __syncthreads();

    if (lastflag) {
        float v = 0.0f;
#pragma unroll
        for (int m = 0; m < NBLK / 128; ++m)
            v += g_partials[tid + 128 * m];
#pragma unroll
        for (int off = 16; off > 0; off >>= 1)
            v += __shfl_xor_sync(0xffffffffu, v, off);
        if ((tid & 31) == 0) red[tid >> 5] = v;
        __syncthreads();
        if (tid == 0) {
            const float tot = (red[0] + red[1]) + (red[2] + red[3]);
            // mean(combined) = sum(2*combined) * 0.5 / 2^23 = tot * 2^-24
            out[0] = tot * 5.9604644775390625e-08f;
        }
    }
}

extern "C" void kernel_launch(void* const* d_in, const int* in_sizes, int n_in,
                              void* d_out, int out_size)
{
    (void)in_sizes; (void)n_in; (void)out_size;
    const float* img1 = (const float*)d_in[0];
    const float* img2 = (const float*)d_in[1];
    const float* fus  = (const float*)d_in[2];

    dim3 grid(4, 8, NB);   // 1024 blocks
    ncc_fused<<<grid, 128>>>(img1, img2, fus, (float*)d_out);
}

// round 6
// speedup vs baseline: 1.4091x; 1.4091x over previous
#include <cuda_runtime.h>
#include <cstdint>

// NCC loss, 9x9 box, SAME zero pad, n=81 (matches reference conv).
// Round 6: Round-4 structure (proven 72.2us) with two surgical fixes:
//   - quad-buffered 3-row stages, wait_group 2 => prefetch distance 3 stages
//     (~1200 cyc, deep past DRAM latency). Uniform commit per iteration.
//   - single __syncthreads per stage (bottom barrier redundant at depth>=3).
// Math identical (rel_err ~6e-8). Deterministic fused reduction.

#define WW 512
#define HH 512
#define NB 32
#define COLS 128
#define STRIPH 64
#define NBLK (4 * 8 * 32)   // 1024 blocks
#define NSTAGE 24           // 72 row-steps / 3 rows per stage
#define VECS_PER_STAGE 306  // 9 row-images * 34 float4

__device__ float        g_partials[NBLK];
__device__ unsigned int g_count = 0;

__device__ __forceinline__ void cp16(uint32_t dst, const float* src, bool ok) {
    asm volatile("cp.async.cg.shared.global [%0], [%1], 16, %2;"
                 :: "r"(dst), "l"(src), "r"(ok ? 16 : 0) : "memory");
}
__device__ __forceinline__ void cp_commit() {
    asm volatile("cp.async.commit_group;" ::: "memory");
}
__device__ __forceinline__ void cp_wait2() {
    asm volatile("cp.async.wait_group 2;" ::: "memory");
}

__global__ __launch_bounds__(128, 5)
void ncc_fused(const float* __restrict__ img1,
               const float* __restrict__ img2,
               const float* __restrict__ fus,
               float* __restrict__ out)
{
    const int tid   = threadIdx.x;
    const int xbase = blockIdx.x * COLS;
    const int ybase = blockIdx.y * STRIPH;
    const int b     = blockIdx.z;

    const size_t base = (size_t)b * (size_t)(HH * WW);
    const float* p1 = img1 + base;
    const float* p2 = img2 + base;
    const float* pf = fus  + base;

    // 4 buffers x (3 imgs x 3 rows) x 136 floats (544B rows, 16B aligned)
    __shared__ float rows[4][9][136];
    __shared__ float red[4];
    __shared__ int   lastflag;

    const uint32_t smem_rows = (uint32_t)__cvta_generic_to_shared(&rows[0][0][0]);

    // ---- stage s into buffer buf: 306 float4 cp.asyncs, flat over threads ----
    auto stage = [&](int s, int buf) {
        const int r0 = ybase - 4 + 3 * s;
#pragma unroll
        for (int it = 0; it < 3; ++it) {
            const int i = tid + 128 * it;
            if (i < VECS_PER_STAGE) {
                const int rowimg = i / 34;          // img*3 + jj
                const int vec    = i - rowimg * 34;
                const int img    = rowimg / 3;
                const int jj     = rowimg - img * 3;
                const int r      = r0 + jj;
                const int gx     = xbase - 4 + vec * 4;
                const bool ok    = (r >= 0) && (r < HH) && (gx >= 0) && (gx < WW);
                const int rc  = r < 0 ? 0 : (r >= HH ? HH - 1 : r);
                const int gxc = gx < 0 ? 0 : (gx > WW - 4 ? WW - 4 : gx);
                const float* p = (img == 0) ? p1 : ((img == 1) ? p2 : pf);
                const uint32_t dst =
                    smem_rows + (uint32_t)(((buf * 9 + rowimg) * 136 + vec * 4) * 4);
                cp16(dst, p + (long)rc * WW + gxc, ok);
            }
        }
    };

    float ring[9][8];
    float S[8];
#pragma unroll
    for (int j = 0; j < 9; ++j)
#pragma unroll
        for (int q = 0; q < 8; ++q) ring[j][q] = 0.0f;
#pragma unroll
    for (int q = 0; q < 8; ++q) S[q] = 0.0f;

    float acc = 0.0f;
    const float inv_n = 1.0f / 81.0f;

    stage(0, 0); cp_commit();
    stage(1, 1); cp_commit();
    stage(2, 2); cp_commit();

    for (int a = 0; a < 8; ++a) {
#pragma unroll
        for (int g = 0; g < 3; ++g) {
            const int s   = 3 * a + g;
            const int buf = s & 3;              // dynamic base; ring slot is static
            // groups pending at this point: s, s+1, s+2 (later ones may be empty).
            // wait_group 2  <=>  stage s has landed.
            cp_wait2();
            __syncthreads();   // staged data visible; also separates last iter's
                               // readers of buf (s+3)&3 from this iter's refill

            if (s + 3 < NSTAGE) stage(s + 3, (s + 3) & 3);
            cp_commit();       // unconditional: uniform group accounting

            const float (*R)[136] = rows[buf];

#pragma unroll
            for (int j = 0; j < 3; ++j) {
                const int slot = 3 * g + j;     // static 0..8 == (9a+slot) % 9

                // ---- horizontal 9-tap sums of the 8 fields ----
                float h0 = 0.f, h1 = 0.f, h2 = 0.f, h3 = 0.f;
                float h4 = 0.f, h5 = 0.f, h6 = 0.f, h7 = 0.f;
#pragma unroll
                for (int k = 0; k < 9; ++k) {
                    const float av = R[0 + j][tid + k];
                    const float cv = R[3 + j][tid + k];
                    const float fv = R[6 + j][tid + k];
                    h0 += av;
                    h1 = fmaf(av, av, h1);
                    h2 = fmaf(av, fv, h2);
                    h3 += cv;
                    h4 = fmaf(cv, cv, h4);
                    h5 = fmaf(cv, fv, h5);
                    h6 += fv;
                    h7 = fmaf(fv, fv, h7);
                }

                // ---- vertical slide (static ring slot) ----
                S[0] += h0 - ring[slot][0]; ring[slot][0] = h0;
                S[1] += h1 - ring[slot][1]; ring[slot][1] = h1;
                S[2] += h2 - ring[slot][2]; ring[slot][2] = h2;
                S[3] += h3 - ring[slot][3]; ring[slot][3] = h3;
                S[4] += h4 - ring[slot][4]; ring[slot][4] = h4;
                S[5] += h5 - ring[slot][5]; ring[slot][5] = h5;
                S[6] += h6 - ring[slot][6]; ring[slot][6] = h6;
                S[7] += h7 - ring[slot][7]; ring[slot][7] = h7;

                // ---- emit output row (row-step i = 9a+slot >= 8) ----
                if (a > 0 || slot >= 8) {
                    const float mA = S[0] * inv_n;
                    const float mB = S[3] * inv_n;
                    const float mJ = S[6] * inv_n;
                    const float crossA = fmaf(-mA, S[6], S[2]);
                    const float varA   = fmaf(-mA, S[0], S[1]);
                    const float varJ   = fmaf(-mJ, S[6], S[7]);
                    const float crossB = fmaf(-mB, S[6], S[5]);
                    const float varB   = fmaf(-mB, S[3], S[4]);
                    const float ccA = crossA * crossA *
                                      __fdividef(1.0f, fmaf(varA, varJ, 1e-5f));
                    const float ccB = crossB * crossB *
                                      __fdividef(1.0f, fmaf(varB, varJ, 1e-5f));
                    acc += (2.0f - ccA - ccB);   // 2 * combined
                }
            }
            // no bottom barrier: next iteration's top __syncthreads protects
            // buffer reuse (depth-4 ring, refill target last read 3 stages ago)
        }
    }

    // ---- deterministic block reduction ----
#pragma unroll
    for (int off = 16; off > 0; off >>= 1)
        acc += __shfl_xor_sync(0xffffffffu, acc, off);
    if ((tid & 31) == 0) red[tid >> 5] = acc;
    __syncthreads();

    const int bidx = (blockIdx.z * 8 + blockIdx.y) * 4 + blockIdx.x;
    if (tid == 0) {
        g_partials[bidx] = (red[0] + red[1]) + (red[2] + red[3]);
        __threadfence();
        unsigned int old = atomicInc(&g_count, NBLK - 1);  // wraps: graph-replay safe
        lastflag = (old == NBLK - 1);
    }
    __syncthreads();

    if (lastflag) {
        float v = 0.0f;
#pragma unroll
        for (int m = 0; m < NBLK / 128; ++m)
            v += g_partials[tid + 128 * m];
#pragma unroll
        for (int off = 16; off > 0; off >>= 1)
            v += __shfl_xor_sync(0xffffffffu, v, off);
        if ((tid & 31) == 0) red[tid >> 5] = v;
        __syncthreads();
        if (tid == 0) {
            const float tot = (red[0] + red[1]) + (red[2] + red[3]);
            // mean(combined) = sum(2*combined) * 0.5 / 2^23 = tot * 2^-24
            out[0] = tot * 5.9604644775390625e-08f;
        }
    }
}

extern "C" void kernel_launch(void* const* d_in, const int* in_sizes, int n_in,
                              void* d_out, int out_size)
{
    (void)in_sizes; (void)n_in; (void)out_size;
    const float* img1 = (const float*)d_in[0];
    const float* img2 = (const float*)d_in[1];
    const float* fus  = (const float*)d_in[2];

    dim3 grid(4, 8, NB);   // 1024 blocks
    ncc_fused<<<grid, 128>>>(img1, img2, fus, (float*)d_out);
}